// round 7
// baseline (speedup 1.0000x reference)
#include <cuda_runtime.h>
#include <cuda_bf16.h>
#include <math.h>

#define FIN 128
#define HC 256            // H*C layer1 output width
#define NH 8              // heads layer 1
#define C2 32             // channels layer 2
#define GG 64             // graphs
#define NCLS 10
#define MAXN 100000
#define MAXE 1600000

// ---------------- scratch (device globals; no allocation allowed) ------------
__device__ __align__(16) unsigned g_h1b[MAXN * (HC / 2)];  // bf16x2 h1 (51.2 MB)
__device__ float g_out1[MAXN * HC];        // elu(gat1 + b1)   (102.4 MB)
__device__ float g_as1[MAXN * NH];
__device__ float g_ad1[MAXN * NH];
__device__ float g_h2[MAXN * C2];
__device__ float g_as2[MAXN];
__device__ float g_ad2[MAXN];
__device__ int   g_deg[MAXN];
__device__ int   g_rowptr[MAXN + 1];
__device__ int   g_cursor[MAXN];
__device__ int   g_csrc[MAXE];
__device__ int   g_bsum[128];
__device__ float g_pool[GG * C2];
__device__ float g_cnt[GG];

__device__ __forceinline__ float lrelu(float v) { return fmaxf(v, 0.2f * v); }

// ---- f32x2 packed-FMA helpers (FFMA2 only reachable via PTX on sm_103a) ----
__device__ __forceinline__ unsigned long long pk2(float lo, float hi) {
    unsigned long long r;
    asm("mov.b64 %0, {%1, %2};" : "=l"(r) : "f"(lo), "f"(hi));
    return r;
}
__device__ __forceinline__ void upk2(unsigned long long v, float& lo, float& hi) {
    asm("mov.b64 {%0, %1}, %2;" : "=f"(lo), "=f"(hi) : "l"(v));
}
__device__ __forceinline__ unsigned long long fma2(unsigned long long a,
                                                   unsigned long long b,
                                                   unsigned long long c) {
    unsigned long long d;
    asm("fma.rn.f32x2 %0, %1, %2, %3;" : "=l"(d) : "l"(a), "l"(b), "l"(c));
    return d;
}
__device__ __forceinline__ unsigned bfpack(float a, float b) {
    __nv_bfloat162 t = __floats2bfloat162_rn(a, b);
    return *reinterpret_cast<unsigned*>(&t);
}
__device__ __forceinline__ float2 bfun(unsigned u) {
    __nv_bfloat162 t = *reinterpret_cast<__nv_bfloat162*>(&u);
    return __bfloat1622float2(t);
}

// ---------------- init ------------------------------------------------------
__global__ void k_init(int n) {
    int g = blockIdx.x * blockDim.x + threadIdx.x;
    if (g < n) g_deg[g] = 0;
    if (g < GG * C2) g_pool[g] = 0.f;
    if (g < GG) g_cnt[g] = 0.f;
}

// ---------------- CSR build: histogram -> scan -> scatter -------------------
__global__ void k_hist(const int* __restrict__ ei, int E) {
    int e = blockIdx.x * blockDim.x + threadIdx.x;
    if (e < E) atomicAdd(&g_deg[ei[E + e]], 1);
}

__global__ void k_scan1(int n) {
    __shared__ int s[1024];
    int t = threadIdx.x;
    int g = blockIdx.x * 1024 + t;
    int v = (g < n) ? g_deg[g] : 0;
    s[t] = v;
    __syncthreads();
    for (int off = 1; off < 1024; off <<= 1) {
        int u = 0;
        if (t >= off) u = s[t - off];
        __syncthreads();
        if (t >= off) s[t] += u;
        __syncthreads();
    }
    if (g < n) g_rowptr[g] = s[t] - v;          // exclusive, chunk-local
    if (t == 1023) g_bsum[blockIdx.x] = s[1023];
}

__global__ void k_scan2(int nb) {              // single block, 128 threads
    __shared__ int s[128];
    int t = threadIdx.x;
    int v = (t < nb) ? g_bsum[t] : 0;
    s[t] = v;
    __syncthreads();
    for (int off = 1; off < 128; off <<= 1) {
        int u = 0;
        if (t >= off) u = s[t - off];
        __syncthreads();
        if (t >= off) s[t] += u;
        __syncthreads();
    }
    if (t < nb) g_bsum[t] = s[t] - v;          // exclusive
}

__global__ void k_scan3(int n, int E) {
    int g = blockIdx.x * 1024 + threadIdx.x;
    if (g < n) {
        int v = g_rowptr[g] + g_bsum[blockIdx.x];
        g_rowptr[g] = v;
        g_cursor[g] = v;
    }
    if (g == 0) g_rowptr[n] = E;
}

__global__ void k_scatter(const int* __restrict__ ei, int E) {
    int e = blockIdx.x * blockDim.x + threadIdx.x;
    if (e < E) {
        int s = ei[e];
        int d = ei[E + e];
        int pos = atomicAdd(&g_cursor[d], 1);
        g_csrc[pos] = s;
    }
}

// ---------------- GEMM1: register-tiled h1 = x @ W1 + scores ----------------
// Block: 256 threads, tile 64 nodes x 256 cols, K=128 in chunks of 16.
// Warp ty owns nodes 8ty..8ty+7; lane tx owns cols 8tx..8tx+7 (head = tx/4).
// Inner loop processes k in QUADS: A fetched as broadcast LDS.128 (1 wavefront
// per 4 k-values) to cut smem wavefronts 16 -> 10 per kk (crossbar was binding).
__global__ void k_gemm1(const float* __restrict__ x, const float* __restrict__ W1,
                        const float* __restrict__ asw, const float* __restrict__ adw,
                        int n) {
    __shared__ float xs[64][FIN];       // 32 KB
    __shared__ float ws[16][HC];        // 16 KB
    int t = threadIdx.x;
    int tx = t & 31, ty = t >> 5;
    int n0 = blockIdx.x * 64;

    for (int idx = t; idx < 64 * (FIN / 4); idx += 256) {
        int nn = idx >> 5, c4 = (idx & 31) << 2;
        float4 v = make_float4(0.f, 0.f, 0.f, 0.f);
        if (n0 + nn < n) v = *(const float4*)&x[(n0 + nn) * FIN + c4];
        *(float4*)&xs[nn][c4] = v;
    }

    unsigned long long acc[8][4];
#pragma unroll
    for (int j = 0; j < 8; j++)
#pragma unroll
        for (int cp = 0; cp < 4; cp++) acc[j][cp] = 0ull;

    for (int kc = 0; kc < FIN / 16; kc++) {
        __syncthreads();
        for (int idx = t; idx < 16 * (HC / 4); idx += 256) {
            int kk = idx >> 6, c4 = (idx & 63) << 2;
            *(float4*)&ws[kk][c4] = *(const float4*)&W1[(kc * 16 + kk) * HC + c4];
        }
        __syncthreads();
#pragma unroll
        for (int kq = 0; kq < 4; kq++) {
            // stage 4 k-values for each of my 8 nodes: broadcast LDS.128
            float4 av[8];
#pragma unroll
            for (int j = 0; j < 8; j++)
                av[j] = *(const float4*)&xs[8 * ty + j][kc * 16 + kq * 4];
#pragma unroll
            for (int q = 0; q < 4; q++) {
                int kk = kq * 4 + q;
                float4 b0 = *(const float4*)&ws[kk][8 * tx];
                float4 b1v = *(const float4*)&ws[kk][8 * tx + 4];
                unsigned long long bp[4];
                bp[0] = pk2(b0.x, b0.y);   bp[1] = pk2(b0.z, b0.w);
                bp[2] = pk2(b1v.x, b1v.y); bp[3] = pk2(b1v.z, b1v.w);
#pragma unroll
                for (int j = 0; j < 8; j++) {
                    float a = (q == 0) ? av[j].x : (q == 1) ? av[j].y
                            : (q == 2) ? av[j].z : av[j].w;
                    unsigned long long a2 = pk2(a, a);
                    acc[j][0] = fma2(a2, bp[0], acc[j][0]);
                    acc[j][1] = fma2(a2, bp[1], acc[j][1]);
                    acc[j][2] = fma2(a2, bp[2], acc[j][2]);
                    acc[j][3] = fma2(a2, bp[3], acc[j][3]);
                }
            }
        }
    }

    float aswv[8], adwv[8];
    {
        float4 s0 = *(const float4*)&asw[8 * tx];
        float4 s1 = *(const float4*)&asw[8 * tx + 4];
        float4 d0 = *(const float4*)&adw[8 * tx];
        float4 d1 = *(const float4*)&adw[8 * tx + 4];
        aswv[0]=s0.x; aswv[1]=s0.y; aswv[2]=s0.z; aswv[3]=s0.w;
        aswv[4]=s1.x; aswv[5]=s1.y; aswv[6]=s1.z; aswv[7]=s1.w;
        adwv[0]=d0.x; adwv[1]=d0.y; adwv[2]=d0.z; adwv[3]=d0.w;
        adwv[4]=d1.x; adwv[5]=d1.y; adwv[6]=d1.z; adwv[7]=d1.w;
    }

#pragma unroll
    for (int j = 0; j < 8; j++) {
        int nn = n0 + 8 * ty + j;
        float v[8];
        upk2(acc[j][0], v[0], v[1]); upk2(acc[j][1], v[2], v[3]);
        upk2(acc[j][2], v[4], v[5]); upk2(acc[j][3], v[6], v[7]);
        if (nn < n) {
            uint4 pkd;
            pkd.x = bfpack(v[0], v[1]); pkd.y = bfpack(v[2], v[3]);
            pkd.z = bfpack(v[4], v[5]); pkd.w = bfpack(v[6], v[7]);
            *(uint4*)&g_h1b[nn * (HC / 2) + 4 * tx] = pkd;
        }
        float vs = 0.f, vd = 0.f;
#pragma unroll
        for (int c = 0; c < 8; c++) { vs += v[c] * aswv[c]; vd += v[c] * adwv[c]; }
        vs += __shfl_xor_sync(0xffffffffu, vs, 1);
        vs += __shfl_xor_sync(0xffffffffu, vs, 2);
        vd += __shfl_xor_sync(0xffffffffu, vd, 1);
        vd += __shfl_xor_sync(0xffffffffu, vd, 2);
        if ((tx & 3) == 0 && nn < n) {
            g_as1[nn * NH + (tx >> 2)] = vs;
            g_ad1[nn * NH + (tx >> 2)] = vd;
        }
    }
}

// ---------------- GAT layer 1: warp/node, fused pass, bf16 gather -----------
// (serial gather loop — the R5 form; explicit pipelining measured slower)
__global__ void k_gat1(const float* __restrict__ b1, int n) {
    __shared__ float ps[8][32 * 9];
    int w = (blockIdx.x * blockDim.x + threadIdx.x) >> 5;
    int lane = threadIdx.x & 31;
    int wl = (threadIdx.x >> 5);
    if (w >= n) return;
    int base = g_rowptr[w];
    int d = g_rowptr[w + 1] - base;
    int h_me = lane >> 2;

    float ad[NH];
    {
        float4 a0 = *(const float4*)&g_ad1[w * NH];
        float4 a1 = *(const float4*)&g_ad1[w * NH + 4];
        ad[0]=a0.x; ad[1]=a0.y; ad[2]=a0.z; ad[3]=a0.w;
        ad[4]=a1.x; ad[5]=a1.y; ad[6]=a1.z; ad[7]=a1.w;
    }
    float psf = __expf(lrelu(g_as1[w * NH + h_me] + ad[h_me]));

    float acc[8];
    {
        uint4 hv = *(const uint4*)&g_h1b[w * (HC / 2) + 4 * lane];
        float2 f0 = bfun(hv.x), f1 = bfun(hv.y), f2 = bfun(hv.z), f3 = bfun(hv.w);
        acc[0] = psf * f0.x; acc[1] = psf * f0.y;
        acc[2] = psf * f1.x; acc[3] = psf * f1.y;
        acc[4] = psf * f2.x; acc[5] = psf * f2.y;
        acc[6] = psf * f3.x; acc[7] = psf * f3.y;
    }
    float z = 0.f;

    for (int c0 = 0; c0 < d; c0 += 32) {
        int i = c0 + lane;
        int s = 0;
        float p[NH];
#pragma unroll
        for (int h = 0; h < NH; h++) p[h] = 0.f;
        if (i < d) {
            s = g_csrc[base + i];
            float4 e0 = *(const float4*)&g_as1[s * NH];
            float4 e1 = *(const float4*)&g_as1[s * NH + 4];
            float ae[NH] = {e0.x, e0.y, e0.z, e0.w, e1.x, e1.y, e1.z, e1.w};
#pragma unroll
            for (int h = 0; h < NH; h++) p[h] = __expf(lrelu(ae[h] + ad[h]));
        }
#pragma unroll
        for (int h = 0; h < NH; h++) ps[wl][lane * 9 + h] = p[h];
        __syncwarp();

        int m = min(32, d - c0);
        for (int j = 0; j < m; j++) {
            int sj = __shfl_sync(0xffffffffu, s, j);
            float pj = ps[wl][j * 9 + h_me];
            z += pj;
            uint4 hv = *(const uint4*)&g_h1b[sj * (HC / 2) + 4 * lane];
            float2 f0 = bfun(hv.x), f1 = bfun(hv.y), f2 = bfun(hv.z), f3 = bfun(hv.w);
            acc[0] += pj * f0.x; acc[1] += pj * f0.y;
            acc[2] += pj * f1.x; acc[3] += pj * f1.y;
            acc[4] += pj * f2.x; acc[5] += pj * f2.y;
            acc[6] += pj * f3.x; acc[7] += pj * f3.y;
        }
        __syncwarp();
    }

    z += psf;
    float invz = 1.f / (z + 1e-16f);
    float4 bb0 = *(const float4*)&b1[8 * lane];
    float4 bb1 = *(const float4*)&b1[8 * lane + 4];
    float bv[8] = {bb0.x, bb0.y, bb0.z, bb0.w, bb1.x, bb1.y, bb1.z, bb1.w};
    float o[8];
#pragma unroll
    for (int c = 0; c < 8; c++) {
        float v = acc[c] * invz + bv[c];
        o[c] = (v > 0.f) ? v : expm1f(v);               // ELU
    }
    *(float4*)&g_out1[w * HC + 8 * lane]     = make_float4(o[0], o[1], o[2], o[3]);
    *(float4*)&g_out1[w * HC + 8 * lane + 4] = make_float4(o[4], o[5], o[6], o[7]);
}

// ---------------- GEMM2: register-tiled h2 = out1 @ W2 (+ scores) -----------
__global__ void k_gemm2(const float* __restrict__ W2, const float* __restrict__ asw2,
                        const float* __restrict__ adw2, int n) {
    __shared__ float ws2[HC][C2];       // 32 KB, loaded once
    __shared__ float xs[128][24];       // per 16-k chunk
    int t = threadIdx.x;
    int tx = t & 7, ty = t >> 3;
    int n0 = blockIdx.x * 128;

    for (int idx = t; idx < HC * (C2 / 4); idx += 256) {
        int kk = idx >> 3, c4 = (idx & 7) << 2;
        *(float4*)&ws2[kk][c4] = *(const float4*)&W2[kk * C2 + c4];
    }

    unsigned long long acc[4][2];
#pragma unroll
    for (int j = 0; j < 4; j++) { acc[j][0] = 0ull; acc[j][1] = 0ull; }

    for (int kc = 0; kc < HC / 16; kc++) {
        __syncthreads();
        for (int idx = t; idx < 128 * 4; idx += 256) {
            int nn = idx >> 2, c4 = (idx & 3) << 2;
            float4 v = make_float4(0.f, 0.f, 0.f, 0.f);
            if (n0 + nn < n) v = *(const float4*)&g_out1[(n0 + nn) * HC + kc * 16 + c4];
            *(float4*)&xs[nn][c4] = v;
        }
        __syncthreads();
#pragma unroll
        for (int kq = 0; kq < 4; kq++) {
            float4 av[4];
#pragma unroll
            for (int j = 0; j < 4; j++)
                av[j] = *(const float4*)&xs[4 * ty + j][kq * 4];
#pragma unroll
            for (int q = 0; q < 4; q++) {
                int kk = kq * 4 + q;
                float4 bw = *(const float4*)&ws2[kc * 16 + kk][4 * tx];
                unsigned long long bp0 = pk2(bw.x, bw.y);
                unsigned long long bp1 = pk2(bw.z, bw.w);
#pragma unroll
                for (int j = 0; j < 4; j++) {
                    float a = (q == 0) ? av[j].x : (q == 1) ? av[j].y
                            : (q == 2) ? av[j].z : av[j].w;
                    unsigned long long a2 = pk2(a, a);
                    acc[j][0] = fma2(a2, bp0, acc[j][0]);
                    acc[j][1] = fma2(a2, bp1, acc[j][1]);
                }
            }
        }
    }

    float aswv[4], adwv[4];
    {
        float4 s0 = *(const float4*)&asw2[4 * tx];
        float4 d0 = *(const float4*)&adw2[4 * tx];
        aswv[0]=s0.x; aswv[1]=s0.y; aswv[2]=s0.z; aswv[3]=s0.w;
        adwv[0]=d0.x; adwv[1]=d0.y; adwv[2]=d0.z; adwv[3]=d0.w;
    }
#pragma unroll
    for (int j = 0; j < 4; j++) {
        int nn = n0 + 4 * ty + j;
        float v[4];
        upk2(acc[j][0], v[0], v[1]);
        upk2(acc[j][1], v[2], v[3]);
        if (nn < n)
            *(float4*)&g_h2[nn * C2 + 4 * tx] = make_float4(v[0], v[1], v[2], v[3]);
        float vs = 0.f, vd = 0.f;
#pragma unroll
        for (int c = 0; c < 4; c++) { vs += v[c] * aswv[c]; vd += v[c] * adwv[c]; }
        vs += __shfl_xor_sync(0xffffffffu, vs, 1);
        vs += __shfl_xor_sync(0xffffffffu, vs, 2);
        vs += __shfl_xor_sync(0xffffffffu, vs, 4);
        vd += __shfl_xor_sync(0xffffffffu, vd, 1);
        vd += __shfl_xor_sync(0xffffffffu, vd, 2);
        vd += __shfl_xor_sync(0xffffffffu, vd, 4);
        if (tx == 0 && nn < n) { g_as2[nn] = vs; g_ad2[nn] = vd; }
    }
}

// -------- GAT layer 2 (1 head), fused pass + pooling (serial gather) --------
__global__ void k_gat2(const float* __restrict__ b2, const int* __restrict__ batch, int n) {
    int w = (blockIdx.x * blockDim.x + threadIdx.x) >> 5;
    int lane = threadIdx.x & 31;
    if (w >= n) return;
    int base = g_rowptr[w];
    int d = g_rowptr[w + 1] - base;
    float adn = g_ad2[w];
    float psf = __expf(lrelu(g_as2[w] + adn));
    float acc = psf * g_h2[w * C2 + lane];
    float z = 0.f;

    for (int c0 = 0; c0 < d; c0 += 32) {
        int i = c0 + lane;
        int s = 0;
        float p = 0.f;
        if (i < d) {
            s = g_csrc[base + i];
            p = __expf(lrelu(g_as2[s] + adn));
            z += p;
        }
        int m = min(32, d - c0);
        for (int j = 0; j < m; j++) {
            int sj = __shfl_sync(0xffffffffu, s, j);
            float pj = __shfl_sync(0xffffffffu, p, j);
            acc += pj * g_h2[sj * C2 + lane];
        }
    }
#pragma unroll
    for (int off = 16; off; off >>= 1)
        z += __shfl_xor_sync(0xffffffffu, z, off);
    z += psf;
    float val = acc / (z + 1e-16f) + b2[lane];
    int g = batch[w];
    atomicAdd(&g_pool[g * C2 + lane], val);
    if (lane == 0) atomicAdd(&g_cnt[g], 1.f);
}

// ---------------- final: mean-pool normalize + linear head ------------------
__global__ void k_final(const float* __restrict__ Wlin, const float* __restrict__ blin,
                        float* __restrict__ out) {
    int t = threadIdx.x;
    if (t >= GG * NCLS) return;
    int g = t / NCLS, c = t - g * NCLS;
    float inv = 1.f / fmaxf(g_cnt[g], 1.f);
    float acc = blin[c];
#pragma unroll
    for (int k = 0; k < C2; k++)
        acc += g_pool[g * C2 + k] * inv * Wlin[k * NCLS + c];
    out[t] = acc;
}

// ---------------- launch ----------------------------------------------------
// gemm1 stays at launch index 3 so ncu profiles it (direct before/after).
extern "C" void kernel_launch(void* const* d_in, const int* in_sizes, int n_in,
                              void* d_out, int out_size) {
    const float* x    = (const float*)d_in[0];
    const int*   ei   = (const int*)d_in[1];
    const int*   batch= (const int*)d_in[2];
    const float* W1   = (const float*)d_in[3];
    const float* asw1 = (const float*)d_in[4];
    const float* adw1 = (const float*)d_in[5];
    const float* b1   = (const float*)d_in[6];
    const float* W2   = (const float*)d_in[7];
    const float* asw2 = (const float*)d_in[8];
    const float* adw2 = (const float*)d_in[9];
    const float* b2   = (const float*)d_in[10];
    const float* Wlin = (const float*)d_in[11];
    const float* blin = (const float*)d_in[12];
    float* out = (float*)d_out;

    int n = in_sizes[0] / FIN;
    int E = in_sizes[1] / 2;
    int nb = (n + 1023) / 1024;

    k_init<<<(n + 255) / 256, 256>>>(n);                       // 0
    k_hist<<<(E + 255) / 256, 256>>>(ei, E);                   // 1
    k_scan1<<<nb, 1024>>>(n);                                  // 2
    k_gemm1<<<(n + 63) / 64, 256>>>(x, W1, asw1, adw1, n);     // 3  <- profiled
    k_scan2<<<1, 128>>>(nb);                                   // 4
    k_scan3<<<nb, 1024>>>(n, E);                               // 5
    k_scatter<<<(E + 255) / 256, 256>>>(ei, E);                // 6
    k_gat1<<<(n + 7) / 8, 256>>>(b1, n);                       // 7
    k_gemm2<<<(n + 127) / 128, 256>>>(W2, asw2, adw2, n);      // 8
    k_gat2<<<(n + 7) / 8, 256>>>(b2, batch, n);                // 9
    k_final<<<1, GG * NCLS>>>(Wlin, blin, out);                // 10
}

// round 10
// speedup vs baseline: 1.4412x; 1.4412x over previous
#include <cuda_runtime.h>
#include <cuda_bf16.h>
#include <math.h>
#include <stdint.h>

#define FIN 128
#define HC 256            // H*C layer1 output width
#define NH 8              // heads layer 1
#define C2 32             // channels layer 2
#define GG 64             // graphs
#define NCLS 10
#define MAXN 100000
#define MAXE 1600000

// ---------------- scratch (device globals; no allocation allowed) ------------
__device__ __align__(16) unsigned g_h1b[MAXN * (HC / 2)];  // bf16x2 h1 (51.2 MB)
__device__ float g_out1[MAXN * HC];        // elu(gat1 + b1)   (102.4 MB)
__device__ float g_as1[MAXN * NH];
__device__ float g_ad1[MAXN * NH];
__device__ float g_h2[MAXN * C2];
__device__ float g_as2[MAXN];
__device__ float g_ad2[MAXN];
__device__ int   g_deg[MAXN];
__device__ int   g_rowptr[MAXN + 1];
__device__ int   g_cursor[MAXN];
__device__ int   g_csrc[MAXE];
__device__ int   g_bsum[128];
__device__ float g_pool[GG * C2];
__device__ float g_cnt[GG];
// W1^T as tf32 (fp32 bits, rna-rounded): row n (output col) x 128 k. 128 KB.
__device__ __align__(16) unsigned g_W1T[HC * FIN];

__device__ __forceinline__ float lrelu(float v) { return fmaxf(v, 0.2f * v); }

// ---- f32x2 packed-FMA helpers (for gemm2) ----------------------------------
__device__ __forceinline__ unsigned long long pk2(float lo, float hi) {
    unsigned long long r;
    asm("mov.b64 %0, {%1, %2};" : "=l"(r) : "f"(lo), "f"(hi));
    return r;
}
__device__ __forceinline__ void upk2(unsigned long long v, float& lo, float& hi) {
    asm("mov.b64 {%0, %1}, %2;" : "=f"(lo), "=f"(hi) : "l"(v));
}
__device__ __forceinline__ unsigned long long fma2(unsigned long long a,
                                                   unsigned long long b,
                                                   unsigned long long c) {
    unsigned long long d;
    asm("fma.rn.f32x2 %0, %1, %2, %3;" : "=l"(d) : "l"(a), "l"(b), "l"(c));
    return d;
}
__device__ __forceinline__ unsigned bfpack(float a, float b) {
    __nv_bfloat162 t = __floats2bfloat162_rn(a, b);
    return *reinterpret_cast<unsigned*>(&t);
}
__device__ __forceinline__ float2 bfun(unsigned u) {
    __nv_bfloat162 t = *reinterpret_cast<__nv_bfloat162*>(&u);
    return __bfloat1622float2(t);
}
__device__ __forceinline__ unsigned tf32cv(float f) {
    unsigned o;
    asm("cvt.rna.tf32.f32 %0, %1;" : "=r"(o) : "f"(f));
    return o;
}
// warp-level tf32 MMA m16n8k8 (sm_80 baseline PTX — compiles for sm_103)
__device__ __forceinline__ void mma_tf32(float* d, unsigned a0, unsigned a1,
                                         unsigned a2, unsigned a3,
                                         unsigned b0, unsigned b1) {
    asm volatile(
        "mma.sync.aligned.m16n8k8.row.col.f32.tf32.tf32.f32 "
        "{%0,%1,%2,%3}, {%4,%5,%6,%7}, {%8,%9}, {%0,%1,%2,%3};"
        : "+f"(d[0]), "+f"(d[1]), "+f"(d[2]), "+f"(d[3])
        : "r"(a0), "r"(a1), "r"(a2), "r"(a3), "r"(b0), "r"(b1));
}

// ---------------- init ------------------------------------------------------
__global__ void k_init(int n) {
    int g = blockIdx.x * blockDim.x + threadIdx.x;
    if (g < n) g_deg[g] = 0;
    if (g < GG * C2) g_pool[g] = 0.f;
    if (g < GG) g_cnt[g] = 0.f;
}

// ---------------- CSR build: histogram -> scan -> scatter -------------------
__global__ void k_hist(const int* __restrict__ ei, int E) {
    int e = blockIdx.x * blockDim.x + threadIdx.x;
    if (e < E) atomicAdd(&g_deg[ei[E + e]], 1);
}

__global__ void k_scan1(int n) {
    __shared__ int s[1024];
    int t = threadIdx.x;
    int g = blockIdx.x * 1024 + t;
    int v = (g < n) ? g_deg[g] : 0;
    s[t] = v;
    __syncthreads();
    for (int off = 1; off < 1024; off <<= 1) {
        int u = 0;
        if (t >= off) u = s[t - off];
        __syncthreads();
        if (t >= off) s[t] += u;
        __syncthreads();
    }
    if (g < n) g_rowptr[g] = s[t] - v;
    if (t == 1023) g_bsum[blockIdx.x] = s[1023];
}

__global__ void k_scan2(int nb) {
    __shared__ int s[128];
    int t = threadIdx.x;
    int v = (t < nb) ? g_bsum[t] : 0;
    s[t] = v;
    __syncthreads();
    for (int off = 1; off < 128; off <<= 1) {
        int u = 0;
        if (t >= off) u = s[t - off];
        __syncthreads();
        if (t >= off) s[t] += u;
        __syncthreads();
    }
    if (t < nb) g_bsum[t] = s[t] - v;
}

__global__ void k_scan3(int n, int E) {
    int g = blockIdx.x * 1024 + threadIdx.x;
    if (g < n) {
        int v = g_rowptr[g] + g_bsum[blockIdx.x];
        g_rowptr[g] = v;
        g_cursor[g] = v;
    }
    if (g == 0) g_rowptr[n] = E;
}

__global__ void k_scatter(const int* __restrict__ ei, int E) {
    int e = blockIdx.x * blockDim.x + threadIdx.x;
    if (e < E) {
        int s = ei[e];
        int d = ei[E + e];
        int pos = atomicAdd(&g_cursor[d], 1);
        g_csrc[pos] = s;
    }
}

// ------- prep: W1^T -> tf32-rounded fp32 image (one-time, tiny) -------------
__global__ void k_prep(const float* __restrict__ W1) {
    int id = blockIdx.x * blockDim.x + threadIdx.x;   // 32768
    int nn = id >> 7, k = id & 127;
    g_W1T[id] = tf32cv(W1[k * HC + nn]);
}

// ---------------- GEMM1 via warp MMA (tf32 in, fp32 acc) --------------------
// Block 256 thr = 8 warps. Tile 64 nodes x 256 cols, K=128.
// Warp: mg=wid>>1 (16 nodes), ng=wid&1 (128 cols) -> 16 m16n8k8 frags x 16 ksteps.
// smem rows padded to 132 words: addr%32 = 4g+tt -> conflict-free frag loads.
#define XW 132
#define SM_XS 0                                   // 64*132 u32
#define SM_WS (64 * XW)
#define SM_AS (SM_WS + HC * XW)
#define SM_AD (SM_AS + HC)
#define SMEM_G1_BYTES ((SM_AD + HC) * 4)          // 171008 B

__global__ void __launch_bounds__(256) k_gemm1(
        const float* __restrict__ x, const float* __restrict__ asw,
        const float* __restrict__ adw, int n) {
    extern __shared__ unsigned sm[];
    unsigned* xs2 = sm + SM_XS;
    unsigned* ws2 = sm + SM_WS;
    float* asw_s = (float*)(sm + SM_AS);
    float* adw_s = (float*)(sm + SM_AD);

    int t = threadIdx.x;
    int wid = t >> 5, lane = t & 31;
    int n0 = blockIdx.x * 64;

    // fill xs: 64 rows x 32 float4-chunks — fp32 -> tf32(rna)
    for (int i = t; i < 64 * 32; i += 256) {
        int row = i >> 5, q = i & 31;
        int node = n0 + row;
        uint4 pkd = make_uint4(0u, 0u, 0u, 0u);
        if (node < n) {
            float4 a = *(const float4*)&x[(size_t)node * FIN + 4 * q];
            pkd.x = tf32cv(a.x); pkd.y = tf32cv(a.y);
            pkd.z = tf32cv(a.z); pkd.w = tf32cv(a.w);
        }
        *(uint4*)&xs2[row * XW + 4 * q] = pkd;    // row*132*4B is 16B-mult
    }
    // fill ws: 256 rows x 32 chunks from pre-rounded g_W1T
    for (int i = t; i < 256 * 32; i += 256) {
        int row = i >> 5, q = i & 31;
        uint4 v = *(const uint4*)&g_W1T[row * FIN + 4 * q];
        *(uint4*)&ws2[row * XW + 4 * q] = v;
    }
    asw_s[t] = asw[t];
    adw_s[t] = adw[t];
    __syncthreads();

    int mg = wid >> 1, ng = wid & 1;
    int g = lane >> 2, tt = lane & 3;
    int row0 = 16 * mg + g;                 // local node rows
    int row1 = row0 + 8;

    float acc[16][4];
#pragma unroll
    for (int f = 0; f < 16; f++) { acc[f][0]=0.f; acc[f][1]=0.f; acc[f][2]=0.f; acc[f][3]=0.f; }

    for (int ks = 0; ks < 16; ks++) {
        unsigned a0 = xs2[row0 * XW + 8 * ks + tt];
        unsigned a1 = xs2[row1 * XW + 8 * ks + tt];
        unsigned a2 = xs2[row0 * XW + 8 * ks + tt + 4];
        unsigned a3 = xs2[row1 * XW + 8 * ks + tt + 4];
#pragma unroll
        for (int f = 0; f < 16; f++) {
            int nn = 128 * ng + 8 * f + g;
            unsigned b0 = ws2[nn * XW + 8 * ks + tt];
            unsigned b1 = ws2[nn * XW + 8 * ks + tt + 4];
            mma_tf32(acc[f], a0, a1, a2, a3, b0, b1);
        }
    }

    // epilogue: stores + attention scores (fp32)
    int node0 = n0 + row0, node1 = n0 + row1;
    float sv0[4], dv0[4], sv1[4], dv1[4];
#pragma unroll
    for (int h = 0; h < 4; h++) { sv0[h]=0.f; dv0[h]=0.f; sv1[h]=0.f; dv1[h]=0.f; }

#pragma unroll
    for (int f = 0; f < 16; f++) {
        int c0 = 128 * ng + 8 * f + 2 * tt;
        float aw0 = asw_s[c0], aw1 = asw_s[c0 + 1];
        float dw0 = adw_s[c0], dw1 = adw_s[c0 + 1];
        int h = f >> 2;
        sv0[h] += acc[f][0] * aw0 + acc[f][1] * aw1;
        dv0[h] += acc[f][0] * dw0 + acc[f][1] * dw1;
        sv1[h] += acc[f][2] * aw0 + acc[f][3] * aw1;
        dv1[h] += acc[f][2] * dw0 + acc[f][3] * dw1;
        unsigned idx = 64 * ng + 4 * f + tt;
        if (node0 < n) g_h1b[(size_t)node0 * (HC / 2) + idx] = bfpack(acc[f][0], acc[f][1]);
        if (node1 < n) g_h1b[(size_t)node1 * (HC / 2) + idx] = bfpack(acc[f][2], acc[f][3]);
    }
#pragma unroll
    for (int h = 0; h < 4; h++) {
        sv0[h] += __shfl_xor_sync(0xffffffffu, sv0[h], 1);
        sv0[h] += __shfl_xor_sync(0xffffffffu, sv0[h], 2);
        dv0[h] += __shfl_xor_sync(0xffffffffu, dv0[h], 1);
        dv0[h] += __shfl_xor_sync(0xffffffffu, dv0[h], 2);
        sv1[h] += __shfl_xor_sync(0xffffffffu, sv1[h], 1);
        sv1[h] += __shfl_xor_sync(0xffffffffu, sv1[h], 2);
        dv1[h] += __shfl_xor_sync(0xffffffffu, dv1[h], 1);
        dv1[h] += __shfl_xor_sync(0xffffffffu, dv1[h], 2);
    }
    if (tt == 0) {
        int hb = 4 * ng;
#pragma unroll
        for (int h = 0; h < 4; h++) {
            if (node0 < n) { g_as1[node0 * NH + hb + h] = sv0[h]; g_ad1[node0 * NH + hb + h] = dv0[h]; }
            if (node1 < n) { g_as1[node1 * NH + hb + h] = sv1[h]; g_ad1[node1 * NH + hb + h] = dv1[h]; }
        }
    }
}

// ---------------- GAT layer 1: warp/node, fused pass, bf16 gather -----------
__global__ void k_gat1(const float* __restrict__ b1, int n) {
    __shared__ float ps[8][32 * 9];
    int w = (blockIdx.x * blockDim.x + threadIdx.x) >> 5;
    int lane = threadIdx.x & 31;
    int wl = (threadIdx.x >> 5);
    if (w >= n) return;
    int base = g_rowptr[w];
    int d = g_rowptr[w + 1] - base;
    int h_me = lane >> 2;

    float ad[NH];
    {
        float4 a0 = *(const float4*)&g_ad1[w * NH];
        float4 a1 = *(const float4*)&g_ad1[w * NH + 4];
        ad[0]=a0.x; ad[1]=a0.y; ad[2]=a0.z; ad[3]=a0.w;
        ad[4]=a1.x; ad[5]=a1.y; ad[6]=a1.z; ad[7]=a1.w;
    }
    float psf = __expf(lrelu(g_as1[w * NH + h_me] + ad[h_me]));

    float acc[8];
    {
        uint4 hv = *(const uint4*)&g_h1b[(size_t)w * (HC / 2) + 4 * lane];
        float2 f0 = bfun(hv.x), f1 = bfun(hv.y), f2 = bfun(hv.z), f3 = bfun(hv.w);
        acc[0] = psf * f0.x; acc[1] = psf * f0.y;
        acc[2] = psf * f1.x; acc[3] = psf * f1.y;
        acc[4] = psf * f2.x; acc[5] = psf * f2.y;
        acc[6] = psf * f3.x; acc[7] = psf * f3.y;
    }
    float z = 0.f;

    for (int c0 = 0; c0 < d; c0 += 32) {
        int i = c0 + lane;
        int s = 0;
        float p[NH];
#pragma unroll
        for (int h = 0; h < NH; h++) p[h] = 0.f;
        if (i < d) {
            s = g_csrc[base + i];
            float4 e0 = *(const float4*)&g_as1[s * NH];
            float4 e1 = *(const float4*)&g_as1[s * NH + 4];
            float ae[NH] = {e0.x, e0.y, e0.z, e0.w, e1.x, e1.y, e1.z, e1.w};
#pragma unroll
            for (int h = 0; h < NH; h++) p[h] = __expf(lrelu(ae[h] + ad[h]));
        }
#pragma unroll
        for (int h = 0; h < NH; h++) ps[wl][lane * 9 + h] = p[h];
        __syncwarp();

        int m = min(32, d - c0);
        for (int j = 0; j < m; j++) {
            int sj = __shfl_sync(0xffffffffu, s, j);
            float pj = ps[wl][j * 9 + h_me];
            z += pj;
            uint4 hv = *(const uint4*)&g_h1b[(size_t)sj * (HC / 2) + 4 * lane];
            float2 f0 = bfun(hv.x), f1 = bfun(hv.y), f2 = bfun(hv.z), f3 = bfun(hv.w);
            acc[0] += pj * f0.x; acc[1] += pj * f0.y;
            acc[2] += pj * f1.x; acc[3] += pj * f1.y;
            acc[4] += pj * f2.x; acc[5] += pj * f2.y;
            acc[6] += pj * f3.x; acc[7] += pj * f3.y;
        }
        __syncwarp();
    }

    z += psf;
    float invz = 1.f / (z + 1e-16f);
    float4 bb0 = *(const float4*)&b1[8 * lane];
    float4 bb1 = *(const float4*)&b1[8 * lane + 4];
    float bv[8] = {bb0.x, bb0.y, bb0.z, bb0.w, bb1.x, bb1.y, bb1.z, bb1.w};
    float o[8];
#pragma unroll
    for (int c = 0; c < 8; c++) {
        float v = acc[c] * invz + bv[c];
        o[c] = (v > 0.f) ? v : expm1f(v);               // ELU
    }
    *(float4*)&g_out1[(size_t)w * HC + 8 * lane]     = make_float4(o[0], o[1], o[2], o[3]);
    *(float4*)&g_out1[(size_t)w * HC + 8 * lane + 4] = make_float4(o[4], o[5], o[6], o[7]);
}

// ---------------- GEMM2: register-tiled h2 = out1 @ W2 (+ scores) -----------
__global__ void k_gemm2(const float* __restrict__ W2, const float* __restrict__ asw2,
                        const float* __restrict__ adw2, int n) {
    __shared__ float ws2[HC][C2];       // 32 KB, loaded once
    __shared__ float xs[128][24];       // per 16-k chunk
    int t = threadIdx.x;
    int tx = t & 7, ty = t >> 3;
    int n0 = blockIdx.x * 128;

    for (int idx = t; idx < HC * (C2 / 4); idx += 256) {
        int kk = idx >> 3, c4 = (idx & 7) << 2;
        *(float4*)&ws2[kk][c4] = *(const float4*)&W2[kk * C2 + c4];
    }

    unsigned long long acc[4][2];
#pragma unroll
    for (int j = 0; j < 4; j++) { acc[j][0] = 0ull; acc[j][1] = 0ull; }

    for (int kc = 0; kc < HC / 16; kc++) {
        __syncthreads();
        for (int idx = t; idx < 128 * 4; idx += 256) {
            int nn = idx >> 2, c4 = (idx & 3) << 2;
            float4 v = make_float4(0.f, 0.f, 0.f, 0.f);
            if (n0 + nn < n) v = *(const float4*)&g_out1[(size_t)(n0 + nn) * HC + kc * 16 + c4];
            *(float4*)&xs[nn][c4] = v;
        }
        __syncthreads();
#pragma unroll
        for (int kk = 0; kk < 16; kk++) {
            float4 bw = *(const float4*)&ws2[kc * 16 + kk][4 * tx];
            unsigned long long bp0 = pk2(bw.x, bw.y);
            unsigned long long bp1 = pk2(bw.z, bw.w);
#pragma unroll
            for (int j = 0; j < 4; j++) {
                float a = xs[4 * ty + j][kk];
                unsigned long long a2 = pk2(a, a);
                acc[j][0] = fma2(a2, bp0, acc[j][0]);
                acc[j][1] = fma2(a2, bp1, acc[j][1]);
            }
        }
    }

    float aswv[4], adwv[4];
    {
        float4 s0 = *(const float4*)&asw2[4 * tx];
        float4 d0 = *(const float4*)&adw2[4 * tx];
        aswv[0]=s0.x; aswv[1]=s0.y; aswv[2]=s0.z; aswv[3]=s0.w;
        adwv[0]=d0.x; adwv[1]=d0.y; adwv[2]=d0.z; adwv[3]=d0.w;
    }
#pragma unroll
    for (int j = 0; j < 4; j++) {
        int nn = n0 + 4 * ty + j;
        float v[4];
        upk2(acc[j][0], v[0], v[1]);
        upk2(acc[j][1], v[2], v[3]);
        if (nn < n)
            *(float4*)&g_h2[(size_t)nn * C2 + 4 * tx] = make_float4(v[0], v[1], v[2], v[3]);
        float vs = 0.f, vd = 0.f;
#pragma unroll
        for (int c = 0; c < 4; c++) { vs += v[c] * aswv[c]; vd += v[c] * adwv[c]; }
        vs += __shfl_xor_sync(0xffffffffu, vs, 1);
        vs += __shfl_xor_sync(0xffffffffu, vs, 2);
        vs += __shfl_xor_sync(0xffffffffu, vs, 4);
        vd += __shfl_xor_sync(0xffffffffu, vd, 1);
        vd += __shfl_xor_sync(0xffffffffu, vd, 2);
        vd += __shfl_xor_sync(0xffffffffu, vd, 4);
        if (tx == 0 && nn < n) { g_as2[nn] = vs; g_ad2[nn] = vd; }
    }
}

// -------- GAT layer 2 (1 head), fused pass + pooling (serial gather) --------
__global__ void k_gat2(const float* __restrict__ b2, const int* __restrict__ batch, int n) {
    int w = (blockIdx.x * blockDim.x + threadIdx.x) >> 5;
    int lane = threadIdx.x & 31;
    if (w >= n) return;
    int base = g_rowptr[w];
    int d = g_rowptr[w + 1] - base;
    float adn = g_ad2[w];
    float psf = __expf(lrelu(g_as2[w] + adn));
    float acc = psf * g_h2[(size_t)w * C2 + lane];
    float z = 0.f;

    for (int c0 = 0; c0 < d; c0 += 32) {
        int i = c0 + lane;
        int s = 0;
        float p = 0.f;
        if (i < d) {
            s = g_csrc[base + i];
            p = __expf(lrelu(g_as2[s] + adn));
            z += p;
        }
        int m = min(32, d - c0);
        for (int j = 0; j < m; j++) {
            int sj = __shfl_sync(0xffffffffu, s, j);
            float pj = __shfl_sync(0xffffffffu, p, j);
            acc += pj * g_h2[(size_t)sj * C2 + lane];
        }
    }
#pragma unroll
    for (int off = 16; off; off >>= 1)
        z += __shfl_xor_sync(0xffffffffu, z, off);
    z += psf;
    float val = acc / (z + 1e-16f) + b2[lane];
    int g = batch[w];
    atomicAdd(&g_pool[g * C2 + lane], val);
    if (lane == 0) atomicAdd(&g_cnt[g], 1.f);
}

// ---------------- final: mean-pool normalize + linear head ------------------
__global__ void k_final(const float* __restrict__ Wlin, const float* __restrict__ blin,
                        float* __restrict__ out) {
    int t = threadIdx.x;
    if (t >= GG * NCLS) return;
    int g = t / NCLS, c = t - g * NCLS;
    float inv = 1.f / fmaxf(g_cnt[g], 1.f);
    float acc = blin[c];
#pragma unroll
    for (int k = 0; k < C2; k++)
        acc += g_pool[g * C2 + k] * inv * Wlin[k * NCLS + c];
    out[t] = acc;
}

// ---------------- launch ----------------------------------------------------
// gemm1 at launch index 3 so ncu profiles it (HMMA tensor pipe expected).
extern "C" void kernel_launch(void* const* d_in, const int* in_sizes, int n_in,
                              void* d_out, int out_size) {
    const float* x    = (const float*)d_in[0];
    const int*   ei   = (const int*)d_in[1];
    const int*   batch= (const int*)d_in[2];
    const float* W1   = (const float*)d_in[3];
    const float* asw1 = (const float*)d_in[4];
    const float* adw1 = (const float*)d_in[5];
    const float* b1   = (const float*)d_in[6];
    const float* W2   = (const float*)d_in[7];
    const float* asw2 = (const float*)d_in[8];
    const float* adw2 = (const float*)d_in[9];
    const float* b2   = (const float*)d_in[10];
    const float* Wlin = (const float*)d_in[11];
    const float* blin = (const float*)d_in[12];
    float* out = (float*)d_out;

    int n = in_sizes[0] / FIN;
    int E = in_sizes[1] / 2;
    int nb = (n + 1023) / 1024;

    cudaFuncSetAttribute(k_gemm1, cudaFuncAttributeMaxDynamicSharedMemorySize,
                         SMEM_G1_BYTES);

    k_init<<<(n + 255) / 256, 256>>>(n);                          // 0
    k_hist<<<(E + 255) / 256, 256>>>(ei, E);                      // 1
    k_prep<<<128, 256>>>(W1);                                     // 2
    k_gemm1<<<(n + 63) / 64, 256, SMEM_G1_BYTES>>>(x, asw1, adw1, n); // 3 <- profiled
    k_scan1<<<nb, 1024>>>(n);                                     // 4
    k_scan2<<<1, 128>>>(nb);                                      // 5
    k_scan3<<<nb, 1024>>>(n, E);                                  // 6
    k_scatter<<<(E + 255) / 256, 256>>>(ei, E);                   // 7
    k_gat1<<<(n + 7) / 8, 256>>>(b1, n);                          // 8
    k_gemm2<<<(n + 127) / 128, 256>>>(W2, asw2, adw2, n);         // 9
    k_gat2<<<(n + 7) / 8, 256>>>(b2, batch, n);                   // 10
    k_final<<<1, GG * NCLS>>>(Wlin, blin, out);                   // 11
}

// round 11
// speedup vs baseline: 1.6286x; 1.1300x over previous
#include <cuda_runtime.h>
#include <cuda_bf16.h>
#include <math.h>
#include <stdint.h>

#define FIN 128
#define HC 256            // H*C layer1 output width
#define NH 8              // heads layer 1
#define C2 32             // channels layer 2
#define GG 64             // graphs
#define NCLS 10
#define MAXN 100000
#define MAXE 1600000

// ---------------- scratch (device globals; no allocation allowed) ------------
__device__ __align__(16) unsigned g_h1b[MAXN * (HC / 2)];  // bf16x2 h1 (51.2 MB)
__device__ float g_out1[MAXN * HC];        // elu(gat1 + b1)   (102.4 MB)
__device__ float g_as1[MAXN * NH];
__device__ float g_ad1[MAXN * NH];
__device__ float g_h2[MAXN * C2];
__device__ float g_as2[MAXN];
__device__ float g_ad2[MAXN];
__device__ int   g_deg[MAXN];
__device__ int   g_rowptr[MAXN + 1];
__device__ int   g_cursor[MAXN];
__device__ int   g_csrc[MAXE];
__device__ int   g_bsum[128];
__device__ float g_pool[GG * C2];
__device__ float g_cnt[GG];
// W1^T as tf32, K-half blocked: [half h][row n][64 k-words]. 128 KB.
__device__ __align__(16) unsigned g_W1T[HC * FIN];

__device__ __forceinline__ float lrelu(float v) { return fmaxf(v, 0.2f * v); }

// ---- f32x2 packed-FMA helpers (for gemm2) ----------------------------------
__device__ __forceinline__ unsigned long long pk2(float lo, float hi) {
    unsigned long long r;
    asm("mov.b64 %0, {%1, %2};" : "=l"(r) : "f"(lo), "f"(hi));
    return r;
}
__device__ __forceinline__ void upk2(unsigned long long v, float& lo, float& hi) {
    asm("mov.b64 {%0, %1}, %2;" : "=f"(lo), "=f"(hi) : "l"(v));
}
__device__ __forceinline__ unsigned long long fma2(unsigned long long a,
                                                   unsigned long long b,
                                                   unsigned long long c) {
    unsigned long long d;
    asm("fma.rn.f32x2 %0, %1, %2, %3;" : "=l"(d) : "l"(a), "l"(b), "l"(c));
    return d;
}
__device__ __forceinline__ unsigned bfpack(float a, float b) {
    __nv_bfloat162 t = __floats2bfloat162_rn(a, b);
    return *reinterpret_cast<unsigned*>(&t);
}
__device__ __forceinline__ float2 bfun(unsigned u) {
    __nv_bfloat162 t = *reinterpret_cast<__nv_bfloat162*>(&u);
    return __bfloat1622float2(t);
}
__device__ __forceinline__ unsigned tf32cv(float f) {
    unsigned o;
    asm("cvt.rna.tf32.f32 %0, %1;" : "=r"(o) : "f"(f));
    return o;
}
// warp-level tf32 MMA m16n8k8 (sm_80 baseline PTX — compiles for sm_103)
__device__ __forceinline__ void mma_tf32(float* d, unsigned a0, unsigned a1,
                                         unsigned a2, unsigned a3,
                                         unsigned b0, unsigned b1) {
    asm volatile(
        "mma.sync.aligned.m16n8k8.row.col.f32.tf32.tf32.f32 "
        "{%0,%1,%2,%3}, {%4,%5,%6,%7}, {%8,%9}, {%0,%1,%2,%3};"
        : "+f"(d[0]), "+f"(d[1]), "+f"(d[2]), "+f"(d[3])
        : "r"(a0), "r"(a1), "r"(a2), "r"(a3), "r"(b0), "r"(b1));
}

// ---------------- init ------------------------------------------------------
__global__ void k_init(int n) {
    int g = blockIdx.x * blockDim.x + threadIdx.x;
    if (g < n) g_deg[g] = 0;
    if (g < GG * C2) g_pool[g] = 0.f;
    if (g < GG) g_cnt[g] = 0.f;
}

// ---------------- CSR build: histogram -> scan -> scatter -------------------
__global__ void k_hist(const int* __restrict__ ei, int E) {
    int e = blockIdx.x * blockDim.x + threadIdx.x;
    if (e < E) atomicAdd(&g_deg[ei[E + e]], 1);
}

__global__ void k_scan1(int n) {
    __shared__ int s[1024];
    int t = threadIdx.x;
    int g = blockIdx.x * 1024 + t;
    int v = (g < n) ? g_deg[g] : 0;
    s[t] = v;
    __syncthreads();
    for (int off = 1; off < 1024; off <<= 1) {
        int u = 0;
        if (t >= off) u = s[t - off];
        __syncthreads();
        if (t >= off) s[t] += u;
        __syncthreads();
    }
    if (g < n) g_rowptr[g] = s[t] - v;
    if (t == 1023) g_bsum[blockIdx.x] = s[1023];
}

__global__ void k_scan2(int nb) {
    __shared__ int s[128];
    int t = threadIdx.x;
    int v = (t < nb) ? g_bsum[t] : 0;
    s[t] = v;
    __syncthreads();
    for (int off = 1; off < 128; off <<= 1) {
        int u = 0;
        if (t >= off) u = s[t - off];
        __syncthreads();
        if (t >= off) s[t] += u;
        __syncthreads();
    }
    if (t < nb) g_bsum[t] = s[t] - v;
}

__global__ void k_scan3(int n, int E) {
    int g = blockIdx.x * 1024 + threadIdx.x;
    if (g < n) {
        int v = g_rowptr[g] + g_bsum[blockIdx.x];
        g_rowptr[g] = v;
        g_cursor[g] = v;
    }
    if (g == 0) g_rowptr[n] = E;
}

__global__ void k_scatter(const int* __restrict__ ei, int E) {
    int e = blockIdx.x * blockDim.x + threadIdx.x;
    if (e < E) {
        int s = ei[e];
        int d = ei[E + e];
        int pos = atomicAdd(&g_cursor[d], 1);
        g_csrc[pos] = s;
    }
}

// ------- prep: W1^T -> tf32 image, K-half blocked (one-time, tiny) ----------
// g_W1T[(h*256 + n)*64 + w] = tf32(W1[(64h + w)*HC + n])
__global__ void k_prep(const float* __restrict__ W1) {
    int id = blockIdx.x * blockDim.x + threadIdx.x;   // 32768
    int h = id >> 14;
    int rem = id & 16383;
    int nn = rem >> 6, w = rem & 63;
    g_W1T[id] = tf32cv(W1[(64 * h + w) * HC + nn]);
}

// ---------------- GEMM1 via warp MMA (tf32 in, fp32 acc) --------------------
// Block 256 thr = 8 warps. Tile 64 nodes x 256 cols, K=128 staged in 2 K-halves
// (B smem halved -> 105.5 KB total -> 2 blocks/SM).
// Warp: mg=wid>>2 (32 nodes, 2 m-frags), ng=wid&3 (64 cols, 8 n-frags).
// Per kstep: 8 A-LDS + 16 B-LDS + 16 MMA (each B frag feeds 2 MMAs).
#define XW 132                                    // xs row words (128 + 4 pad)
#define WW 68                                     // ws row words (64 + 4 pad)
#define SM_XS 0                                   // 64*132  = 8448 words
#define SM_WS (64 * XW)                           // 256*68  = 17408 words
#define SM_AS (SM_WS + HC * WW)
#define SM_AD (SM_AS + HC)
#define SMEM_G1_BYTES ((SM_AD + HC) * 4)          // 105472 B

__global__ void __launch_bounds__(256, 2) k_gemm1(
        const float* __restrict__ x, const float* __restrict__ asw,
        const float* __restrict__ adw, int n) {
    extern __shared__ unsigned sm[];
    unsigned* xs2 = sm + SM_XS;
    unsigned* ws2 = sm + SM_WS;
    float* asw_s = (float*)(sm + SM_AS);
    float* adw_s = (float*)(sm + SM_AD);

    int t = threadIdx.x;
    int wid = t >> 5, lane = t & 31;
    int n0 = blockIdx.x * 64;

    // fill xs: 64 rows x 32 float4-chunks — fp32 -> tf32(rna), full K
    for (int i = t; i < 64 * 32; i += 256) {
        int row = i >> 5, q = i & 31;
        int node = n0 + row;
        uint4 pkd = make_uint4(0u, 0u, 0u, 0u);
        if (node < n) {
            float4 a = *(const float4*)&x[(size_t)node * FIN + 4 * q];
            pkd.x = tf32cv(a.x); pkd.y = tf32cv(a.y);
            pkd.z = tf32cv(a.z); pkd.w = tf32cv(a.w);
        }
        *(uint4*)&xs2[row * XW + 4 * q] = pkd;
    }
    asw_s[t] = asw[t];
    adw_s[t] = adw[t];

    int mg = wid >> 2, ng = wid & 3;
    int g = lane >> 2, tt = lane & 3;

    float acc[2][8][4];
#pragma unroll
    for (int mi = 0; mi < 2; mi++)
#pragma unroll
        for (int f = 0; f < 8; f++) {
            acc[mi][f][0] = 0.f; acc[mi][f][1] = 0.f;
            acc[mi][f][2] = 0.f; acc[mi][f][3] = 0.f;
        }

    for (int h = 0; h < 2; h++) {
        __syncthreads();
        // fill ws for K-half h: 256 rows x 16 uint4
        for (int i = t; i < 256 * 16; i += 256) {
            int row = i >> 4, q = i & 15;
            uint4 v = *(const uint4*)&g_W1T[(h * 256 + row) * 64 + 4 * q];
            *(uint4*)&ws2[row * WW + 4 * q] = v;
        }
        __syncthreads();
#pragma unroll
        for (int ks = 0; ks < 8; ks++) {
            int ak = 64 * h + 8 * ks;
            unsigned a[2][4];
#pragma unroll
            for (int mi = 0; mi < 2; mi++) {
                int r0 = (32 * mg + 16 * mi + g) * XW + ak;
                a[mi][0] = xs2[r0 + tt];
                a[mi][1] = xs2[r0 + 8 * XW + tt];
                a[mi][2] = xs2[r0 + tt + 4];
                a[mi][3] = xs2[r0 + 8 * XW + tt + 4];
            }
#pragma unroll
            for (int f = 0; f < 8; f++) {
                int bn = (64 * ng + 8 * f + g) * WW + 8 * ks;
                unsigned b0 = ws2[bn + tt];
                unsigned b1 = ws2[bn + tt + 4];
                mma_tf32(acc[0][f], a[0][0], a[0][1], a[0][2], a[0][3], b0, b1);
                mma_tf32(acc[1][f], a[1][0], a[1][1], a[1][2], a[1][3], b0, b1);
            }
        }
    }

    // epilogue: h1 bf16 store + attention scores (fp32)
#pragma unroll
    for (int mi = 0; mi < 2; mi++) {
        int node0 = n0 + 32 * mg + 16 * mi + g;
        int node1 = node0 + 8;
        float sv0[2] = {0.f, 0.f}, dv0[2] = {0.f, 0.f};
        float sv1[2] = {0.f, 0.f}, dv1[2] = {0.f, 0.f};
#pragma unroll
        for (int f = 0; f < 8; f++) {
            int c0 = 64 * ng + 8 * f + 2 * tt;
            float aw0 = asw_s[c0], aw1 = asw_s[c0 + 1];
            float dw0 = adw_s[c0], dw1 = adw_s[c0 + 1];
            int hh = f >> 2;
            float* A = acc[mi][f];
            sv0[hh] += A[0] * aw0 + A[1] * aw1;
            dv0[hh] += A[0] * dw0 + A[1] * dw1;
            sv1[hh] += A[2] * aw0 + A[3] * aw1;
            dv1[hh] += A[2] * dw0 + A[3] * dw1;
            unsigned idx = 32 * ng + 4 * f + tt;
            if (node0 < n) g_h1b[(size_t)node0 * (HC / 2) + idx] = bfpack(A[0], A[1]);
            if (node1 < n) g_h1b[(size_t)node1 * (HC / 2) + idx] = bfpack(A[2], A[3]);
        }
#pragma unroll
        for (int hh = 0; hh < 2; hh++) {
            sv0[hh] += __shfl_xor_sync(0xffffffffu, sv0[hh], 1);
            sv0[hh] += __shfl_xor_sync(0xffffffffu, sv0[hh], 2);
            dv0[hh] += __shfl_xor_sync(0xffffffffu, dv0[hh], 1);
            dv0[hh] += __shfl_xor_sync(0xffffffffu, dv0[hh], 2);
            sv1[hh] += __shfl_xor_sync(0xffffffffu, sv1[hh], 1);
            sv1[hh] += __shfl_xor_sync(0xffffffffu, sv1[hh], 2);
            dv1[hh] += __shfl_xor_sync(0xffffffffu, dv1[hh], 1);
            dv1[hh] += __shfl_xor_sync(0xffffffffu, dv1[hh], 2);
        }
        if (tt == 0) {
#pragma unroll
            for (int hh = 0; hh < 2; hh++) {
                int hd = 2 * ng + hh;
                if (node0 < n) { g_as1[node0 * NH + hd] = sv0[hh]; g_ad1[node0 * NH + hd] = dv0[hh]; }
                if (node1 < n) { g_as1[node1 * NH + hd] = sv1[hh]; g_ad1[node1 * NH + hd] = dv1[hh]; }
            }
        }
    }
}

// ---------------- GAT layer 1: warp/node, fused pass, bf16 gather -----------
__global__ void k_gat1(const float* __restrict__ b1, int n) {
    __shared__ float ps[8][32 * 9];
    int w = (blockIdx.x * blockDim.x + threadIdx.x) >> 5;
    int lane = threadIdx.x & 31;
    int wl = (threadIdx.x >> 5);
    if (w >= n) return;
    int base = g_rowptr[w];
    int d = g_rowptr[w + 1] - base;
    int h_me = lane >> 2;

    float ad[NH];
    {
        float4 a0 = *(const float4*)&g_ad1[w * NH];
        float4 a1 = *(const float4*)&g_ad1[w * NH + 4];
        ad[0]=a0.x; ad[1]=a0.y; ad[2]=a0.z; ad[3]=a0.w;
        ad[4]=a1.x; ad[5]=a1.y; ad[6]=a1.z; ad[7]=a1.w;
    }
    float psf = __expf(lrelu(g_as1[w * NH + h_me] + ad[h_me]));

    float acc[8];
    {
        uint4 hv = *(const uint4*)&g_h1b[(size_t)w * (HC / 2) + 4 * lane];
        float2 f0 = bfun(hv.x), f1 = bfun(hv.y), f2 = bfun(hv.z), f3 = bfun(hv.w);
        acc[0] = psf * f0.x; acc[1] = psf * f0.y;
        acc[2] = psf * f1.x; acc[3] = psf * f1.y;
        acc[4] = psf * f2.x; acc[5] = psf * f2.y;
        acc[6] = psf * f3.x; acc[7] = psf * f3.y;
    }
    float z = 0.f;

    for (int c0 = 0; c0 < d; c0 += 32) {
        int i = c0 + lane;
        int s = 0;
        float p[NH];
#pragma unroll
        for (int h = 0; h < NH; h++) p[h] = 0.f;
        if (i < d) {
            s = g_csrc[base + i];
            float4 e0 = *(const float4*)&g_as1[s * NH];
            float4 e1 = *(const float4*)&g_as1[s * NH + 4];
            float ae[NH] = {e0.x, e0.y, e0.z, e0.w, e1.x, e1.y, e1.z, e1.w};
#pragma unroll
            for (int h = 0; h < NH; h++) p[h] = __expf(lrelu(ae[h] + ad[h]));
        }
#pragma unroll
        for (int h = 0; h < NH; h++) ps[wl][lane * 9 + h] = p[h];
        __syncwarp();

        int m = min(32, d - c0);
        for (int j = 0; j < m; j++) {
            int sj = __shfl_sync(0xffffffffu, s, j);
            float pj = ps[wl][j * 9 + h_me];
            z += pj;
            uint4 hv = *(const uint4*)&g_h1b[(size_t)sj * (HC / 2) + 4 * lane];
            float2 f0 = bfun(hv.x), f1 = bfun(hv.y), f2 = bfun(hv.z), f3 = bfun(hv.w);
            acc[0] += pj * f0.x; acc[1] += pj * f0.y;
            acc[2] += pj * f1.x; acc[3] += pj * f1.y;
            acc[4] += pj * f2.x; acc[5] += pj * f2.y;
            acc[6] += pj * f3.x; acc[7] += pj * f3.y;
        }
        __syncwarp();
    }

    z += psf;
    float invz = 1.f / (z + 1e-16f);
    float4 bb0 = *(const float4*)&b1[8 * lane];
    float4 bb1 = *(const float4*)&b1[8 * lane + 4];
    float bv[8] = {bb0.x, bb0.y, bb0.z, bb0.w, bb1.x, bb1.y, bb1.z, bb1.w};
    float o[8];
#pragma unroll
    for (int c = 0; c < 8; c++) {
        float v = acc[c] * invz + bv[c];
        o[c] = (v > 0.f) ? v : expm1f(v);               // ELU
    }
    *(float4*)&g_out1[(size_t)w * HC + 8 * lane]     = make_float4(o[0], o[1], o[2], o[3]);
    *(float4*)&g_out1[(size_t)w * HC + 8 * lane + 4] = make_float4(o[4], o[5], o[6], o[7]);
}

// ---------------- GEMM2: register-tiled h2 = out1 @ W2 (+ scores) -----------
__global__ void k_gemm2(const float* __restrict__ W2, const float* __restrict__ asw2,
                        const float* __restrict__ adw2, int n) {
    __shared__ float ws2[HC][C2];       // 32 KB, loaded once
    __shared__ float xs[128][24];       // per 16-k chunk
    int t = threadIdx.x;
    int tx = t & 7, ty = t >> 3;
    int n0 = blockIdx.x * 128;

    for (int idx = t; idx < HC * (C2 / 4); idx += 256) {
        int kk = idx >> 3, c4 = (idx & 7) << 2;
        *(float4*)&ws2[kk][c4] = *(const float4*)&W2[kk * C2 + c4];
    }

    unsigned long long acc[4][2];
#pragma unroll
    for (int j = 0; j < 4; j++) { acc[j][0] = 0ull; acc[j][1] = 0ull; }

    for (int kc = 0; kc < HC / 16; kc++) {
        __syncthreads();
        for (int idx = t; idx < 128 * 4; idx += 256) {
            int nn = idx >> 2, c4 = (idx & 3) << 2;
            float4 v = make_float4(0.f, 0.f, 0.f, 0.f);
            if (n0 + nn < n) v = *(const float4*)&g_out1[(size_t)(n0 + nn) * HC + kc * 16 + c4];
            *(float4*)&xs[nn][c4] = v;
        }
        __syncthreads();
#pragma unroll
        for (int kk = 0; kk < 16; kk++) {
            float4 bw = *(const float4*)&ws2[kc * 16 + kk][4 * tx];
            unsigned long long bp0 = pk2(bw.x, bw.y);
            unsigned long long bp1 = pk2(bw.z, bw.w);
#pragma unroll
            for (int j = 0; j < 4; j++) {
                float a = xs[4 * ty + j][kk];
                unsigned long long a2 = pk2(a, a);
                acc[j][0] = fma2(a2, bp0, acc[j][0]);
                acc[j][1] = fma2(a2, bp1, acc[j][1]);
            }
        }
    }

    float aswv[4], adwv[4];
    {
        float4 s0 = *(const float4*)&asw2[4 * tx];
        float4 d0 = *(const float4*)&adw2[4 * tx];
        aswv[0]=s0.x; aswv[1]=s0.y; aswv[2]=s0.z; aswv[3]=s0.w;
        adwv[0]=d0.x; adwv[1]=d0.y; adwv[2]=d0.z; adwv[3]=d0.w;
    }
#pragma unroll
    for (int j = 0; j < 4; j++) {
        int nn = n0 + 4 * ty + j;
        float v[4];
        upk2(acc[j][0], v[0], v[1]);
        upk2(acc[j][1], v[2], v[3]);
        if (nn < n)
            *(float4*)&g_h2[(size_t)nn * C2 + 4 * tx] = make_float4(v[0], v[1], v[2], v[3]);
        float vs = 0.f, vd = 0.f;
#pragma unroll
        for (int c = 0; c < 4; c++) { vs += v[c] * aswv[c]; vd += v[c] * adwv[c]; }
        vs += __shfl_xor_sync(0xffffffffu, vs, 1);
        vs += __shfl_xor_sync(0xffffffffu, vs, 2);
        vs += __shfl_xor_sync(0xffffffffu, vs, 4);
        vd += __shfl_xor_sync(0xffffffffu, vd, 1);
        vd += __shfl_xor_sync(0xffffffffu, vd, 2);
        vd += __shfl_xor_sync(0xffffffffu, vd, 4);
        if (tx == 0 && nn < n) { g_as2[nn] = vs; g_ad2[nn] = vd; }
    }
}

// -------- GAT layer 2 (1 head), fused pass + pooling (serial gather) --------
__global__ void k_gat2(const float* __restrict__ b2, const int* __restrict__ batch, int n) {
    int w = (blockIdx.x * blockDim.x + threadIdx.x) >> 5;
    int lane = threadIdx.x & 31;
    if (w >= n) return;
    int base = g_rowptr[w];
    int d = g_rowptr[w + 1] - base;
    float adn = g_ad2[w];
    float psf = __expf(lrelu(g_as2[w] + adn));
    float acc = psf * g_h2[(size_t)w * C2 + lane];
    float z = 0.f;

    for (int c0 = 0; c0 < d; c0 += 32) {
        int i = c0 + lane;
        int s = 0;
        float p = 0.f;
        if (i < d) {
            s = g_csrc[base + i];
            p = __expf(lrelu(g_as2[s] + adn));
            z += p;
        }
        int m = min(32, d - c0);
        for (int j = 0; j < m; j++) {
            int sj = __shfl_sync(0xffffffffu, s, j);
            float pj = __shfl_sync(0xffffffffu, p, j);
            acc += pj * g_h2[(size_t)sj * C2 + lane];
        }
    }
#pragma unroll
    for (int off = 16; off; off >>= 1)
        z += __shfl_xor_sync(0xffffffffu, z, off);
    z += psf;
    float val = acc / (z + 1e-16f) + b2[lane];
    int g = batch[w];
    atomicAdd(&g_pool[g * C2 + lane], val);
    if (lane == 0) atomicAdd(&g_cnt[g], 1.f);
}

// ---------------- final: mean-pool normalize + linear head ------------------
__global__ void k_final(const float* __restrict__ Wlin, const float* __restrict__ blin,
                        float* __restrict__ out) {
    int t = threadIdx.x;
    if (t >= GG * NCLS) return;
    int g = t / NCLS, c = t - g * NCLS;
    float inv = 1.f / fmaxf(g_cnt[g], 1.f);
    float acc = blin[c];
#pragma unroll
    for (int k = 0; k < C2; k++)
        acc += g_pool[g * C2 + k] * inv * Wlin[k * NCLS + c];
    out[t] = acc;
}

// ---------------- launch ----------------------------------------------------
// gemm1 at launch index 3 so ncu profiles it (direct before/after on occ fix).
extern "C" void kernel_launch(void* const* d_in, const int* in_sizes, int n_in,
                              void* d_out, int out_size) {
    const float* x    = (const float*)d_in[0];
    const int*   ei   = (const int*)d_in[1];
    const int*   batch= (const int*)d_in[2];
    const float* W1   = (const float*)d_in[3];
    const float* asw1 = (const float*)d_in[4];
    const float* adw1 = (const float*)d_in[5];
    const float* b1   = (const float*)d_in[6];
    const float* W2   = (const float*)d_in[7];
    const float* asw2 = (const float*)d_in[8];
    const float* adw2 = (const float*)d_in[9];
    const float* b2   = (const float*)d_in[10];
    const float* Wlin = (const float*)d_in[11];
    const float* blin = (const float*)d_in[12];
    float* out = (float*)d_out;

    int n = in_sizes[0] / FIN;
    int E = in_sizes[1] / 2;
    int nb = (n + 1023) / 1024;

    cudaFuncSetAttribute(k_gemm1, cudaFuncAttributeMaxDynamicSharedMemorySize,
                         SMEM_G1_BYTES);

    k_init<<<(n + 255) / 256, 256>>>(n);                          // 0
    k_hist<<<(E + 255) / 256, 256>>>(ei, E);                      // 1
    k_prep<<<128, 256>>>(W1);                                     // 2
    k_gemm1<<<(n + 63) / 64, 256, SMEM_G1_BYTES>>>(x, asw1, adw1, n); // 3 <- profiled
    k_scan1<<<nb, 1024>>>(n);                                     // 4
    k_scan2<<<1, 128>>>(nb);                                      // 5
    k_scan3<<<nb, 1024>>>(n, E);                                  // 6
    k_scatter<<<(E + 255) / 256, 256>>>(ei, E);                   // 7
    k_gat1<<<(n + 7) / 8, 256>>>(b1, n);                          // 8
    k_gemm2<<<(n + 127) / 128, 256>>>(W2, asw2, adw2, n);         // 9
    k_gat2<<<(n + 7) / 8, 256>>>(b2, batch, n);                   // 10
    k_final<<<1, GG * NCLS>>>(Wlin, blin, out);                   // 11
}

// round 12
// speedup vs baseline: 1.8343x; 1.1263x over previous
#include <cuda_runtime.h>
#include <cuda_bf16.h>
#include <math.h>
#include <stdint.h>

#define FIN 128
#define HC 256            // H*C layer1 output width
#define NH 8              // heads layer 1
#define C2 32             // channels layer 2
#define GG 64             // graphs
#define NCLS 10
#define MAXN 100000
#define MAXE 1600000

// ---------------- scratch (device globals; no allocation allowed) ------------
__device__ __align__(16) unsigned g_h1b[MAXN * (HC / 2)];  // bf16x2 h1 (51.2 MB)
__device__ float g_out1[MAXN * HC];        // elu(gat1 + b1)   (102.4 MB)
__device__ float g_as1[MAXN * NH];
__device__ float g_ad1[MAXN * NH];
__device__ float g_h2[MAXN * C2];
__device__ float g_as2[MAXN];
__device__ float g_ad2[MAXN];
__device__ int   g_deg[MAXN];
__device__ int   g_rowptr[MAXN + 1];
__device__ int   g_cursor[MAXN];
__device__ int   g_csrc[MAXE];
__device__ int   g_bsum[128];
__device__ float g_pool[GG * C2];
__device__ float g_cnt[GG];
// W1^T as tf32, K-half blocked: [half h][row n][64 k-words]. 128 KB.
__device__ __align__(16) unsigned g_W1T[HC * FIN];
// W2^T as tf32: [col n (32)][k (256)]. 32 KB.
__device__ __align__(16) unsigned g_W2T[C2 * HC];

__device__ __forceinline__ float lrelu(float v) { return fmaxf(v, 0.2f * v); }

__device__ __forceinline__ unsigned bfpack(float a, float b) {
    __nv_bfloat162 t = __floats2bfloat162_rn(a, b);
    return *reinterpret_cast<unsigned*>(&t);
}
__device__ __forceinline__ float2 bfun(unsigned u) {
    __nv_bfloat162 t = *reinterpret_cast<__nv_bfloat162*>(&u);
    return __bfloat1622float2(t);
}
__device__ __forceinline__ unsigned tf32cv(float f) {
    unsigned o;
    asm("cvt.rna.tf32.f32 %0, %1;" : "=r"(o) : "f"(f));
    return o;
}
// warp-level tf32 MMA m16n8k8 (sm_80 baseline PTX — compiles for sm_103)
__device__ __forceinline__ void mma_tf32(float* d, unsigned a0, unsigned a1,
                                         unsigned a2, unsigned a3,
                                         unsigned b0, unsigned b1) {
    asm volatile(
        "mma.sync.aligned.m16n8k8.row.col.f32.tf32.tf32.f32 "
        "{%0,%1,%2,%3}, {%4,%5,%6,%7}, {%8,%9}, {%0,%1,%2,%3};"
        : "+f"(d[0]), "+f"(d[1]), "+f"(d[2]), "+f"(d[3])
        : "r"(a0), "r"(a1), "r"(a2), "r"(a3), "r"(b0), "r"(b1));
}

// ---------------- init ------------------------------------------------------
__global__ void k_init(int n) {
    int g = blockIdx.x * blockDim.x + threadIdx.x;
    if (g < n) g_deg[g] = 0;
    if (g < GG * C2) g_pool[g] = 0.f;
    if (g < GG) g_cnt[g] = 0.f;
}

// ---------------- CSR build: histogram -> scan -> scatter -------------------
__global__ void k_hist(const int* __restrict__ ei, int E) {
    int e = blockIdx.x * blockDim.x + threadIdx.x;
    if (e < E) atomicAdd(&g_deg[ei[E + e]], 1);
}

__global__ void k_scan1(int n) {
    __shared__ int s[1024];
    int t = threadIdx.x;
    int g = blockIdx.x * 1024 + t;
    int v = (g < n) ? g_deg[g] : 0;
    s[t] = v;
    __syncthreads();
    for (int off = 1; off < 1024; off <<= 1) {
        int u = 0;
        if (t >= off) u = s[t - off];
        __syncthreads();
        if (t >= off) s[t] += u;
        __syncthreads();
    }
    if (g < n) g_rowptr[g] = s[t] - v;
    if (t == 1023) g_bsum[blockIdx.x] = s[1023];
}

__global__ void k_scan2(int nb) {
    __shared__ int s[128];
    int t = threadIdx.x;
    int v = (t < nb) ? g_bsum[t] : 0;
    s[t] = v;
    __syncthreads();
    for (int off = 1; off < 128; off <<= 1) {
        int u = 0;
        if (t >= off) u = s[t - off];
        __syncthreads();
        if (t >= off) s[t] += u;
        __syncthreads();
    }
    if (t < nb) g_bsum[t] = s[t] - v;
}

__global__ void k_scan3(int n, int E) {
    int g = blockIdx.x * 1024 + threadIdx.x;
    if (g < n) {
        int v = g_rowptr[g] + g_bsum[blockIdx.x];
        g_rowptr[g] = v;
        g_cursor[g] = v;
    }
    if (g == 0) g_rowptr[n] = E;
}

__global__ void k_scatter(const int* __restrict__ ei, int E) {
    int e = blockIdx.x * blockDim.x + threadIdx.x;
    if (e < E) {
        int s = ei[e];
        int d = ei[E + e];
        int pos = atomicAdd(&g_cursor[d], 1);
        g_csrc[pos] = s;
    }
}

// ------- prep: W1^T -> tf32 image, K-half blocked (one-time, tiny) ----------
__global__ void k_prep(const float* __restrict__ W1) {
    int id = blockIdx.x * blockDim.x + threadIdx.x;   // 32768
    int h = id >> 14;
    int rem = id & 16383;
    int nn = rem >> 6, w = rem & 63;
    g_W1T[id] = tf32cv(W1[(64 * h + w) * HC + nn]);
}

// ------- prep2: W2^T -> tf32 image ------------------------------------------
__global__ void k_prep2(const float* __restrict__ W2) {
    int id = blockIdx.x * blockDim.x + threadIdx.x;   // 8192
    int nn = id >> 8, k = id & 255;
    g_W2T[id] = tf32cv(W2[k * C2 + nn]);
}

// ---------------- GEMM1 via warp MMA (tf32 in, fp32 acc) --------------------
#define XW 132                                    // xs row words (128 + 4 pad)
#define WW 68                                     // ws row words (64 + 4 pad)
#define SM_XS 0
#define SM_WS (64 * XW)
#define SM_AS (SM_WS + HC * WW)
#define SM_AD (SM_AS + HC)
#define SMEM_G1_BYTES ((SM_AD + HC) * 4)          // 105472 B

__global__ void __launch_bounds__(256, 2) k_gemm1(
        const float* __restrict__ x, const float* __restrict__ asw,
        const float* __restrict__ adw, int n) {
    extern __shared__ unsigned sm[];
    unsigned* xs2 = sm + SM_XS;
    unsigned* ws2 = sm + SM_WS;
    float* asw_s = (float*)(sm + SM_AS);
    float* adw_s = (float*)(sm + SM_AD);

    int t = threadIdx.x;
    int wid = t >> 5, lane = t & 31;
    int n0 = blockIdx.x * 64;

    for (int i = t; i < 64 * 32; i += 256) {
        int row = i >> 5, q = i & 31;
        int node = n0 + row;
        uint4 pkd = make_uint4(0u, 0u, 0u, 0u);
        if (node < n) {
            float4 a = *(const float4*)&x[(size_t)node * FIN + 4 * q];
            pkd.x = tf32cv(a.x); pkd.y = tf32cv(a.y);
            pkd.z = tf32cv(a.z); pkd.w = tf32cv(a.w);
        }
        *(uint4*)&xs2[row * XW + 4 * q] = pkd;
    }
    asw_s[t] = asw[t];
    adw_s[t] = adw[t];

    int mg = wid >> 2, ng = wid & 3;
    int g = lane >> 2, tt = lane & 3;

    float acc[2][8][4];
#pragma unroll
    for (int mi = 0; mi < 2; mi++)
#pragma unroll
        for (int f = 0; f < 8; f++) {
            acc[mi][f][0] = 0.f; acc[mi][f][1] = 0.f;
            acc[mi][f][2] = 0.f; acc[mi][f][3] = 0.f;
        }

    for (int h = 0; h < 2; h++) {
        __syncthreads();
        for (int i = t; i < 256 * 16; i += 256) {
            int row = i >> 4, q = i & 15;
            uint4 v = *(const uint4*)&g_W1T[(h * 256 + row) * 64 + 4 * q];
            *(uint4*)&ws2[row * WW + 4 * q] = v;
        }
        __syncthreads();
#pragma unroll
        for (int ks = 0; ks < 8; ks++) {
            int ak = 64 * h + 8 * ks;
            unsigned a[2][4];
#pragma unroll
            for (int mi = 0; mi < 2; mi++) {
                int r0 = (32 * mg + 16 * mi + g) * XW + ak;
                a[mi][0] = xs2[r0 + tt];
                a[mi][1] = xs2[r0 + 8 * XW + tt];
                a[mi][2] = xs2[r0 + tt + 4];
                a[mi][3] = xs2[r0 + 8 * XW + tt + 4];
            }
#pragma unroll
            for (int f = 0; f < 8; f++) {
                int bn = (64 * ng + 8 * f + g) * WW + 8 * ks;
                unsigned b0 = ws2[bn + tt];
                unsigned b1 = ws2[bn + tt + 4];
                mma_tf32(acc[0][f], a[0][0], a[0][1], a[0][2], a[0][3], b0, b1);
                mma_tf32(acc[1][f], a[1][0], a[1][1], a[1][2], a[1][3], b0, b1);
            }
        }
    }

#pragma unroll
    for (int mi = 0; mi < 2; mi++) {
        int node0 = n0 + 32 * mg + 16 * mi + g;
        int node1 = node0 + 8;
        float sv0[2] = {0.f, 0.f}, dv0[2] = {0.f, 0.f};
        float sv1[2] = {0.f, 0.f}, dv1[2] = {0.f, 0.f};
#pragma unroll
        for (int f = 0; f < 8; f++) {
            int c0 = 64 * ng + 8 * f + 2 * tt;
            float aw0 = asw_s[c0], aw1 = asw_s[c0 + 1];
            float dw0 = adw_s[c0], dw1 = adw_s[c0 + 1];
            int hh = f >> 2;
            float* A = acc[mi][f];
            sv0[hh] += A[0] * aw0 + A[1] * aw1;
            dv0[hh] += A[0] * dw0 + A[1] * dw1;
            sv1[hh] += A[2] * aw0 + A[3] * aw1;
            dv1[hh] += A[2] * dw0 + A[3] * dw1;
            unsigned idx = 32 * ng + 4 * f + tt;
            if (node0 < n) g_h1b[(size_t)node0 * (HC / 2) + idx] = bfpack(A[0], A[1]);
            if (node1 < n) g_h1b[(size_t)node1 * (HC / 2) + idx] = bfpack(A[2], A[3]);
        }
#pragma unroll
        for (int hh = 0; hh < 2; hh++) {
            sv0[hh] += __shfl_xor_sync(0xffffffffu, sv0[hh], 1);
            sv0[hh] += __shfl_xor_sync(0xffffffffu, sv0[hh], 2);
            dv0[hh] += __shfl_xor_sync(0xffffffffu, dv0[hh], 1);
            dv0[hh] += __shfl_xor_sync(0xffffffffu, dv0[hh], 2);
            sv1[hh] += __shfl_xor_sync(0xffffffffu, sv1[hh], 1);
            sv1[hh] += __shfl_xor_sync(0xffffffffu, sv1[hh], 2);
            dv1[hh] += __shfl_xor_sync(0xffffffffu, dv1[hh], 1);
            dv1[hh] += __shfl_xor_sync(0xffffffffu, dv1[hh], 2);
        }
        if (tt == 0) {
#pragma unroll
            for (int hh = 0; hh < 2; hh++) {
                int hd = 2 * ng + hh;
                if (node0 < n) { g_as1[node0 * NH + hd] = sv0[hh]; g_ad1[node0 * NH + hd] = dv0[hh]; }
                if (node1 < n) { g_as1[node1 * NH + hd] = sv1[hh]; g_ad1[node1 * NH + hd] = dv1[hh]; }
            }
        }
    }
}

// ---------------- GAT layer 1: warp/node, fused pass, bf16 gather -----------
// Inner gather unrolled x4 (no predicates in main body; scalar tail).
__global__ void k_gat1(const float* __restrict__ b1, int n) {
    __shared__ float ps[8][32 * 9];
    int w = (blockIdx.x * blockDim.x + threadIdx.x) >> 5;
    int lane = threadIdx.x & 31;
    int wl = (threadIdx.x >> 5);
    if (w >= n) return;
    int base = g_rowptr[w];
    int d = g_rowptr[w + 1] - base;
    int h_me = lane >> 2;

    float ad[NH];
    {
        float4 a0 = *(const float4*)&g_ad1[w * NH];
        float4 a1 = *(const float4*)&g_ad1[w * NH + 4];
        ad[0]=a0.x; ad[1]=a0.y; ad[2]=a0.z; ad[3]=a0.w;
        ad[4]=a1.x; ad[5]=a1.y; ad[6]=a1.z; ad[7]=a1.w;
    }
    float psf = __expf(lrelu(g_as1[w * NH + h_me] + ad[h_me]));

    float acc[8];
    {
        uint4 hv = *(const uint4*)&g_h1b[(size_t)w * (HC / 2) + 4 * lane];
        float2 f0 = bfun(hv.x), f1 = bfun(hv.y), f2 = bfun(hv.z), f3 = bfun(hv.w);
        acc[0] = psf * f0.x; acc[1] = psf * f0.y;
        acc[2] = psf * f1.x; acc[3] = psf * f1.y;
        acc[4] = psf * f2.x; acc[5] = psf * f2.y;
        acc[6] = psf * f3.x; acc[7] = psf * f3.y;
    }
    float z = 0.f;

    for (int c0 = 0; c0 < d; c0 += 32) {
        int i = c0 + lane;
        int s = 0;
        float p[NH];
#pragma unroll
        for (int h = 0; h < NH; h++) p[h] = 0.f;
        if (i < d) {
            s = g_csrc[base + i];
            float4 e0 = *(const float4*)&g_as1[s * NH];
            float4 e1 = *(const float4*)&g_as1[s * NH + 4];
            float ae[NH] = {e0.x, e0.y, e0.z, e0.w, e1.x, e1.y, e1.z, e1.w};
#pragma unroll
            for (int h = 0; h < NH; h++) p[h] = __expf(lrelu(ae[h] + ad[h]));
        }
#pragma unroll
        for (int h = 0; h < NH; h++) ps[wl][lane * 9 + h] = p[h];
        __syncwarp();

        int m = min(32, d - c0);
        int j = 0;
        for (; j + 4 <= m; j += 4) {
            int s0 = __shfl_sync(0xffffffffu, s, j);
            int s1 = __shfl_sync(0xffffffffu, s, j + 1);
            int s2 = __shfl_sync(0xffffffffu, s, j + 2);
            int s3 = __shfl_sync(0xffffffffu, s, j + 3);
            uint4 h0 = *(const uint4*)&g_h1b[(size_t)s0 * (HC / 2) + 4 * lane];
            uint4 h1 = *(const uint4*)&g_h1b[(size_t)s1 * (HC / 2) + 4 * lane];
            uint4 h2 = *(const uint4*)&g_h1b[(size_t)s2 * (HC / 2) + 4 * lane];
            uint4 h3 = *(const uint4*)&g_h1b[(size_t)s3 * (HC / 2) + 4 * lane];
            float p0 = ps[wl][(j + 0) * 9 + h_me];
            float p1 = ps[wl][(j + 1) * 9 + h_me];
            float p2 = ps[wl][(j + 2) * 9 + h_me];
            float p3 = ps[wl][(j + 3) * 9 + h_me];
            z += p0 + p1 + p2 + p3;
            {
                float2 f0 = bfun(h0.x), f1 = bfun(h0.y), f2 = bfun(h0.z), f3 = bfun(h0.w);
                acc[0] += p0 * f0.x; acc[1] += p0 * f0.y;
                acc[2] += p0 * f1.x; acc[3] += p0 * f1.y;
                acc[4] += p0 * f2.x; acc[5] += p0 * f2.y;
                acc[6] += p0 * f3.x; acc[7] += p0 * f3.y;
            }
            {
                float2 f0 = bfun(h1.x), f1 = bfun(h1.y), f2 = bfun(h1.z), f3 = bfun(h1.w);
                acc[0] += p1 * f0.x; acc[1] += p1 * f0.y;
                acc[2] += p1 * f1.x; acc[3] += p1 * f1.y;
                acc[4] += p1 * f2.x; acc[5] += p1 * f2.y;
                acc[6] += p1 * f3.x; acc[7] += p1 * f3.y;
            }
            {
                float2 f0 = bfun(h2.x), f1 = bfun(h2.y), f2 = bfun(h2.z), f3 = bfun(h2.w);
                acc[0] += p2 * f0.x; acc[1] += p2 * f0.y;
                acc[2] += p2 * f1.x; acc[3] += p2 * f1.y;
                acc[4] += p2 * f2.x; acc[5] += p2 * f2.y;
                acc[6] += p2 * f3.x; acc[7] += p2 * f3.y;
            }
            {
                float2 f0 = bfun(h3.x), f1 = bfun(h3.y), f2 = bfun(h3.z), f3 = bfun(h3.w);
                acc[0] += p3 * f0.x; acc[1] += p3 * f0.y;
                acc[2] += p3 * f1.x; acc[3] += p3 * f1.y;
                acc[4] += p3 * f2.x; acc[5] += p3 * f2.y;
                acc[6] += p3 * f3.x; acc[7] += p3 * f3.y;
            }
        }
        for (; j < m; j++) {
            int sj = __shfl_sync(0xffffffffu, s, j);
            float pj = ps[wl][j * 9 + h_me];
            z += pj;
            uint4 hv = *(const uint4*)&g_h1b[(size_t)sj * (HC / 2) + 4 * lane];
            float2 f0 = bfun(hv.x), f1 = bfun(hv.y), f2 = bfun(hv.z), f3 = bfun(hv.w);
            acc[0] += pj * f0.x; acc[1] += pj * f0.y;
            acc[2] += pj * f1.x; acc[3] += pj * f1.y;
            acc[4] += pj * f2.x; acc[5] += pj * f2.y;
            acc[6] += pj * f3.x; acc[7] += pj * f3.y;
        }
        __syncwarp();
    }

    z += psf;
    float invz = 1.f / (z + 1e-16f);
    float4 bb0 = *(const float4*)&b1[8 * lane];
    float4 bb1 = *(const float4*)&b1[8 * lane + 4];
    float bv[8] = {bb0.x, bb0.y, bb0.z, bb0.w, bb1.x, bb1.y, bb1.z, bb1.w};
    float o[8];
#pragma unroll
    for (int c = 0; c < 8; c++) {
        float v = acc[c] * invz + bv[c];
        o[c] = (v > 0.f) ? v : expm1f(v);               // ELU
    }
    *(float4*)&g_out1[(size_t)w * HC + 8 * lane]     = make_float4(o[0], o[1], o[2], o[3]);
    *(float4*)&g_out1[(size_t)w * HC + 8 * lane + 4] = make_float4(o[4], o[5], o[6], o[7]);
}

// ---------------- GEMM2 via warp MMA (tf32 in, fp32 acc) --------------------
// Block 256 thr = 8 warps. Tile 128 nodes x 32 cols, K=256 in 4 chunks of 64.
// Warp wid: 16 nodes (rows 16wid..16wid+15), all 32 cols (4 n-frags m16n8k8).
#define S2_XA 0                                   // 128*68 words
#define S2_WB (128 * 68)                          // 32*260 words
#define S2_AS (S2_WB + 32 * 260)
#define S2_AD (S2_AS + 32)
#define SMEM_G2_BYTES ((S2_AD + 32) * 4)          // 68352 B

__global__ void __launch_bounds__(256) k_gemm2(
        const float* __restrict__ asw2, const float* __restrict__ adw2, int n) {
    extern __shared__ unsigned sm2[];
    unsigned* xa = sm2 + S2_XA;
    unsigned* wb = sm2 + S2_WB;
    float* as_s = (float*)(sm2 + S2_AS);
    float* ad_s = (float*)(sm2 + S2_AD);

    int t = threadIdx.x;
    int wid = t >> 5, lane = t & 31;
    int g = lane >> 2, tt = lane & 3;
    int n0 = blockIdx.x * 128;

    // fill B (tf32 W2^T) once: 32 rows x 64 k-quads
    for (int i = t; i < 32 * 64; i += 256) {
        int row = i >> 6, q = i & 63;
        uint4 v = *(const uint4*)&g_W2T[row * 256 + 4 * q];
        *(uint4*)&wb[row * 260 + 4 * q] = v;
    }
    if (t < 32) { as_s[t] = asw2[t]; ad_s[t] = adw2[t]; }

    float acc[4][4];
#pragma unroll
    for (int f = 0; f < 4; f++) { acc[f][0]=0.f; acc[f][1]=0.f; acc[f][2]=0.f; acc[f][3]=0.f; }

    for (int kc = 0; kc < 4; kc++) {
        __syncthreads();
        // fill A chunk: 128 nodes x 64 k words, fp32 -> tf32
        for (int i = t; i < 128 * 16; i += 256) {
            int row = i >> 4, q = i & 15;
            int node = n0 + row;
            uint4 pkd = make_uint4(0u, 0u, 0u, 0u);
            if (node < n) {
                float4 a = *(const float4*)&g_out1[(size_t)node * HC + kc * 64 + 4 * q];
                pkd.x = tf32cv(a.x); pkd.y = tf32cv(a.y);
                pkd.z = tf32cv(a.z); pkd.w = tf32cv(a.w);
            }
            *(uint4*)&xa[row * 68 + 4 * q] = pkd;
        }
        __syncthreads();
#pragma unroll
        for (int ks = 0; ks < 8; ks++) {
            int r0 = (16 * wid + g) * 68 + 8 * ks;
            unsigned a0 = xa[r0 + tt];
            unsigned a1 = xa[r0 + 8 * 68 + tt];
            unsigned a2 = xa[r0 + tt + 4];
            unsigned a3 = xa[r0 + 8 * 68 + tt + 4];
#pragma unroll
            for (int f = 0; f < 4; f++) {
                int bn = (8 * f + g) * 260 + kc * 64 + 8 * ks;
                unsigned b0 = wb[bn + tt];
                unsigned b1 = wb[bn + tt + 4];
                mma_tf32(acc[f], a0, a1, a2, a3, b0, b1);
            }
        }
    }

    // epilogue: h2 store + attention scores
    int node0 = n0 + 16 * wid + g;
    int node1 = node0 + 8;
    float vs0 = 0.f, vd0 = 0.f, vs1 = 0.f, vd1 = 0.f;
#pragma unroll
    for (int f = 0; f < 4; f++) {
        int c = 8 * f + 2 * tt;
        float aw0 = as_s[c], aw1 = as_s[c + 1];
        float dw0 = ad_s[c], dw1 = ad_s[c + 1];
        vs0 += acc[f][0] * aw0 + acc[f][1] * aw1;
        vd0 += acc[f][0] * dw0 + acc[f][1] * dw1;
        vs1 += acc[f][2] * aw0 + acc[f][3] * aw1;
        vd1 += acc[f][2] * dw0 + acc[f][3] * dw1;
        if (node0 < n) *(float2*)&g_h2[(size_t)node0 * C2 + c] = make_float2(acc[f][0], acc[f][1]);
        if (node1 < n) *(float2*)&g_h2[(size_t)node1 * C2 + c] = make_float2(acc[f][2], acc[f][3]);
    }
    vs0 += __shfl_xor_sync(0xffffffffu, vs0, 1);
    vs0 += __shfl_xor_sync(0xffffffffu, vs0, 2);
    vd0 += __shfl_xor_sync(0xffffffffu, vd0, 1);
    vd0 += __shfl_xor_sync(0xffffffffu, vd0, 2);
    vs1 += __shfl_xor_sync(0xffffffffu, vs1, 1);
    vs1 += __shfl_xor_sync(0xffffffffu, vs1, 2);
    vd1 += __shfl_xor_sync(0xffffffffu, vd1, 1);
    vd1 += __shfl_xor_sync(0xffffffffu, vd1, 2);
    if (tt == 0) {
        if (node0 < n) { g_as2[node0] = vs0; g_ad2[node0] = vd0; }
        if (node1 < n) { g_as2[node1] = vs1; g_ad2[node1] = vd1; }
    }
}

// -------- GAT layer 2 (1 head), fused pass + pooling (serial gather) --------
__global__ void k_gat2(const float* __restrict__ b2, const int* __restrict__ batch, int n) {
    int w = (blockIdx.x * blockDim.x + threadIdx.x) >> 5;
    int lane = threadIdx.x & 31;
    if (w >= n) return;
    int base = g_rowptr[w];
    int d = g_rowptr[w + 1] - base;
    float adn = g_ad2[w];
    float psf = __expf(lrelu(g_as2[w] + adn));
    float acc = psf * g_h2[(size_t)w * C2 + lane];
    float z = 0.f;

    for (int c0 = 0; c0 < d; c0 += 32) {
        int i = c0 + lane;
        int s = 0;
        float p = 0.f;
        if (i < d) {
            s = g_csrc[base + i];
            p = __expf(lrelu(g_as2[s] + adn));
            z += p;
        }
        int m = min(32, d - c0);
        for (int j = 0; j < m; j++) {
            int sj = __shfl_sync(0xffffffffu, s, j);
            float pj = __shfl_sync(0xffffffffu, p, j);
            acc += pj * g_h2[(size_t)sj * C2 + lane];
        }
    }
#pragma unroll
    for (int off = 16; off; off >>= 1)
        z += __shfl_xor_sync(0xffffffffu, z, off);
    z += psf;
    float val = acc / (z + 1e-16f) + b2[lane];
    int g = batch[w];
    atomicAdd(&g_pool[g * C2 + lane], val);
    if (lane == 0) atomicAdd(&g_cnt[g], 1.f);
}

// ---------------- final: mean-pool normalize + linear head ------------------
__global__ void k_final(const float* __restrict__ Wlin, const float* __restrict__ blin,
                        float* __restrict__ out) {
    int t = threadIdx.x;
    if (t >= GG * NCLS) return;
    int g = t / NCLS, c = t - g * NCLS;
    float inv = 1.f / fmaxf(g_cnt[g], 1.f);
    float acc = blin[c];
#pragma unroll
    for (int k = 0; k < C2; k++)
        acc += g_pool[g * C2 + k] * inv * Wlin[k * NCLS + c];
    out[t] = acc;
}

// ---------------- launch ----------------------------------------------------
// gemm1 stays at launch index 3 (profiled slot).
extern "C" void kernel_launch(void* const* d_in, const int* in_sizes, int n_in,
                              void* d_out, int out_size) {
    const float* x    = (const float*)d_in[0];
    const int*   ei   = (const int*)d_in[1];
    const int*   batch= (const int*)d_in[2];
    const float* W1   = (const float*)d_in[3];
    const float* asw1 = (const float*)d_in[4];
    const float* adw1 = (const float*)d_in[5];
    const float* b1   = (const float*)d_in[6];
    const float* W2   = (const float*)d_in[7];
    const float* asw2 = (const float*)d_in[8];
    const float* adw2 = (const float*)d_in[9];
    const float* b2   = (const float*)d_in[10];
    const float* Wlin = (const float*)d_in[11];
    const float* blin = (const float*)d_in[12];
    float* out = (float*)d_out;

    int n = in_sizes[0] / FIN;
    int E = in_sizes[1] / 2;
    int nb = (n + 1023) / 1024;

    cudaFuncSetAttribute(k_gemm1, cudaFuncAttributeMaxDynamicSharedMemorySize,
                         SMEM_G1_BYTES);
    cudaFuncSetAttribute(k_gemm2, cudaFuncAttributeMaxDynamicSharedMemorySize,
                         SMEM_G2_BYTES);

    k_init<<<(n + 255) / 256, 256>>>(n);                          // 0
    k_hist<<<(E + 255) / 256, 256>>>(ei, E);                      // 1
    k_prep<<<128, 256>>>(W1);                                     // 2
    k_gemm1<<<(n + 63) / 64, 256, SMEM_G1_BYTES>>>(x, asw1, adw1, n); // 3 <- profiled
    k_prep2<<<32, 256>>>(W2);                                     // 4
    k_scan1<<<nb, 1024>>>(n);                                     // 5
    k_scan2<<<1, 128>>>(nb);                                      // 6
    k_scan3<<<nb, 1024>>>(n, E);                                  // 7
    k_scatter<<<(E + 255) / 256, 256>>>(ei, E);                   // 8
    k_gat1<<<(n + 7) / 8, 256>>>(b1, n);                          // 9
    k_gemm2<<<(n + 127) / 128, 256, SMEM_G2_BYTES>>>(asw2, adw2, n); // 10
    k_gat2<<<(n + 7) / 8, 256>>>(b2, batch, n);                   // 11
    k_final<<<1, GG * NCLS>>>(Wlin, blin, out);                   // 12
}